// round 14
// baseline (speedup 1.0000x reference)
#include <cuda_runtime.h>
#include <math.h>
#include <stdint.h>
#include <stddef.h>

#define BB   32
#define TT   4096
#define TP   1024
#define DD   64
#define HH   512
#define G4   2048
#define OUTD 6
#define NCTA 128

typedef unsigned long long ULL;
__device__ __forceinline__ ULL ffma2(ULL a, ULL b, ULL c) {
    ULL d; asm("fma.rn.f32x2 %0, %1, %2, %3;" : "=l"(d) : "l"(a), "l"(b), "l"(c)); return d;
}
__device__ __forceinline__ ULL pack2(float lo, float hi) {
    ULL r; asm("mov.b64 %0, {%1, %2};" : "=l"(r) : "f"(lo), "f"(hi)); return r;
}
__device__ __forceinline__ float2 unpack2(ULL v) {
    float2 r; asm("mov.b64 {%0, %1}, %2;" : "=f"(r.x), "=f"(r.y) : "l"(v)); return r;
}
__device__ __forceinline__ float fsigmoid(float x) { return __fdividef(1.f, 1.f + __expf(-x)); }
__device__ __forceinline__ float ftanh(float x) { return 1.f - __fdividef(2.f, __expf(2.f * x) + 1.f); }
__device__ __forceinline__ int ld_acq(const int* p) {
    int v; asm volatile("ld.global.acquire.gpu.b32 %0, [%1];" : "=r"(v) : "l"(p) : "memory"); return v;
}
__device__ __forceinline__ void st_rel(int* p, int v) {
    asm volatile("st.global.release.gpu.b32 [%0], %1;" :: "l"(p), "r"(v) : "memory");
}

// ---------------- scratch ----------------
static __device__ float d_sig[BB * TT];
static __device__ float d_c1 [BB * 64 * 2048];
static __device__ float d_c2 [BB * 64 * 1024];
static __device__ float d_ze [BB * TP * DD];
static __device__ float d_z  [BB * TP * DD];                 // t-major: [t*32+b][64]
static __device__ float d_xgT[(size_t)TP * G4 * BB];         // [t][n][b]
static __device__ float d_h1sT[(size_t)TP * HH * BB];        // [t][j][b]
static __device__ float d_hcat[2 * 1024 * BB];               // [slot][kk][b]
static __device__ int   d_flags2[NCTA];

// ---------------- tokenizer ----------------
__global__ void k_mean(const float* __restrict__ x) {
    int idx = blockIdx.x * 256 + threadIdx.x;
    const float4* xp = (const float4*)x + (size_t)idx * 16;
    float s = 0.f;
#pragma unroll
    for (int i = 0; i < 16; i++) { float4 v = xp[i]; s += v.x + v.y + v.z + v.w; }
    d_sig[idx] = s * (1.0f / 64.0f);
}

__global__ void k_conv1(const float* __restrict__ w1, const float* __restrict__ b1) {
    __shared__ float ws[256], bs[64];
    int tid = threadIdx.x;
    if (tid < 256) ws[tid] = w1[tid];
    if (tid < 64)  bs[tid] = b1[tid];
    __syncthreads();
    int b = blockIdx.y, p = blockIdx.x * 256 + tid;
    const float* sg = d_sig + (size_t)b * TT;
    float in[4];
#pragma unroll
    for (int j = 0; j < 4; j++) {
        int q = 2 * p + j - 1;
        in[j] = (q >= 0 && q < TT) ? sg[q] : 0.f;
    }
    for (int o = 0; o < 64; o++) {
        float a = bs[o];
#pragma unroll
        for (int j = 0; j < 4; j++) a = fmaf(ws[o * 4 + j], in[j], a);
        d_c1[((size_t)(b * 64 + o)) * 2048 + p] = fmaxf(a, 0.f);
    }
}

template<int KS, int STR, int LIN, bool CL>
__global__ void k_conv(const float* __restrict__ src, const float* __restrict__ w,
                       const float* __restrict__ b, float* __restrict__ dst) {
    const int PW = 32 * STR + KS - 1;
    extern __shared__ float sm[];
    float* ws    = sm;
    float* patch = ws + 4096 * KS;
    float* bs    = patch + 64 * PW;
    int tid = threadIdx.x;
    for (int i = tid; i < 4096 * KS; i += 256) ws[i] = w[i];
    if (tid < 64) bs[tid] = b[tid];
    int bb = blockIdx.y, p0 = blockIdx.x * 32, q0 = STR * p0 - 1;
    for (int i = tid; i < 64 * PW; i += 256) {
        int c = i / PW, q = q0 + i % PW;
        patch[i] = (q >= 0 && q < LIN) ? src[((size_t)(bb * 64 + c)) * LIN + q] : 0.f;
    }
    __syncthreads();
    int po = tid & 31, og = tid >> 5;
    float acc[8];
#pragma unroll
    for (int i = 0; i < 8; i++) acc[i] = 0.f;
    for (int c = 0; c < 64; c++) {
        const float* pc = patch + c * PW + STR * po;
        float iv[KS];
#pragma unroll
        for (int j = 0; j < KS; j++) iv[j] = pc[j];
#pragma unroll
        for (int oi = 0; oi < 8; oi++) {
            const float* wp = &ws[((og * 8 + oi) * 64 + c) * KS];
#pragma unroll
            for (int j = 0; j < KS; j++) acc[oi] = fmaf(wp[j], iv[j], acc[oi]);
        }
    }
#pragma unroll
    for (int oi = 0; oi < 8; oi++) {
        int o = og * 8 + oi;
        float v = acc[oi] + bs[o];
        if (CL) dst[((size_t)(bb * TP) + p0 + po) * 64 + o] = v;
        else    dst[((size_t)(bb * 64 + o)) * (LIN / STR) + p0 + po] = fmaxf(v, 0.f);
    }
}

__global__ void k_quant(const float* __restrict__ cb) {
    extern __shared__ float smq[];
    float* cbs = smq;
    float* cn  = smq + 16384;
    int tid = threadIdx.x;
    for (int i = tid; i < 16384; i += 128) cbs[i] = cb[i];
    __syncthreads();
    for (int c = tid; c < 256; c += 128) {
        float s = 0.f;
        const float* cp = cbs + c * 64;
#pragma unroll
        for (int d = 0; d < 64; d++) s = fmaf(cp[d], cp[d], s);
        cn[c] = s;
    }
    __syncthreads();
    int g = blockIdx.x * 128 + tid;          // b*TP + p
    float4 zr[16];
    const float4* zp = (const float4*)d_ze + (size_t)g * 16;
    float szz = 0.f;
#pragma unroll
    for (int i = 0; i < 16; i++) {
        zr[i] = zp[i];
        szz += zr[i].x * zr[i].x + zr[i].y * zr[i].y + zr[i].z * zr[i].z + zr[i].w * zr[i].w;
    }
    float best = 3.0e38f; int bi = 0;
    for (int c = 0; c < 256; c++) {
        const float4* cp = (const float4*)cbs + c * 16;
        float dot = 0.f;
#pragma unroll
        for (int i = 0; i < 16; i++) {
            float4 w = cp[i];
            dot = fmaf(w.x, zr[i].x, fmaf(w.y, zr[i].y, fmaf(w.z, zr[i].z, fmaf(w.w, zr[i].w, dot))));
        }
        float dist = szz - 2.f * dot + cn[c];
        if (dist < best) { best = dist; bi = c; }
    }
    int b = g >> 10, p = g & 1023;
    float4* zo = (float4*)d_z + ((size_t)p * 32 + b) * 16;   // t-major rows
    const float4* cbest = (const float4*)cbs + bi * 16;
#pragma unroll
    for (int i = 0; i < 16; i++) zo[i] = cbest[i];
}

// ---------------- GEMM (f32x2): C = A[M,K]*B[N,K]^T + bias; TR: C -> [t][n][b] ----------------
template<bool TR>
__global__ void __launch_bounds__(256, 2) k_gemm2(
    const float* __restrict__ A, const float* __restrict__ B,
    const float* __restrict__ bias, float* __restrict__ C, int M, int N, int K)
{
    __shared__ float As[16][132];
    __shared__ float Bs[16][128];
    int tid = threadIdx.x;
    int bm = blockIdx.y << 7, bn = blockIdx.x << 7;
    int ty = tid >> 5, tx = tid & 31;
    ULL acc[8][4];
#pragma unroll
    for (int p = 0; p < 8; p++)
#pragma unroll
        for (int j = 0; j < 4; j++) acc[p][j] = 0ULL;
    for (int k0 = 0; k0 < K; k0 += 16) {
        __syncthreads();
#pragma unroll
        for (int q = 0; q < 2; q++) {
            int i = tid * 2 + q, r = i >> 2, c4 = (i & 3) << 2;
            float4 av = *(const float4*)(A + (size_t)(bm + r) * K + k0 + c4);
            As[c4 + 0][r] = av.x; As[c4 + 1][r] = av.y; As[c4 + 2][r] = av.z; As[c4 + 3][r] = av.w;
            float4 bv = *(const float4*)(B + (size_t)(bn + r) * K + k0 + c4);
            Bs[c4 + 0][r] = bv.x; Bs[c4 + 1][r] = bv.y; Bs[c4 + 2][r] = bv.z; Bs[c4 + 3][r] = bv.w;
        }
        __syncthreads();
#pragma unroll 4
        for (int k = 0; k < 16; k++) {
            const ulonglong2* ap = (const ulonglong2*)&As[k][ty << 4];
            ulonglong2 aA = ap[0], aB2 = ap[1], aC = ap[2], aD = ap[3];
            float4 b4 = *(const float4*)&Bs[k][tx << 2];
            ULL d0 = pack2(b4.x, b4.x), d1 = pack2(b4.y, b4.y);
            ULL d2 = pack2(b4.z, b4.z), d3 = pack2(b4.w, b4.w);
#define ROWF(p, P) \
            acc[p][0] = ffma2(P, d0, acc[p][0]); acc[p][1] = ffma2(P, d1, acc[p][1]); \
            acc[p][2] = ffma2(P, d2, acc[p][2]); acc[p][3] = ffma2(P, d3, acc[p][3]);
            ROWF(0, aA.x)  ROWF(1, aA.y)  ROWF(2, aB2.x) ROWF(3, aB2.y)
            ROWF(4, aC.x)  ROWF(5, aC.y)  ROWF(6, aD.x)  ROWF(7, aD.y)
#undef ROWF
        }
    }
    float b0 = bias[bn + (tx << 2)], b1 = bias[bn + (tx << 2) + 1];
    float b2 = bias[bn + (tx << 2) + 2], b3 = bias[bn + (tx << 2) + 3];
#pragma unroll
    for (int p = 0; p < 8; p++) {
        float2 v0 = unpack2(acc[p][0]), v1 = unpack2(acc[p][1]);
        float2 v2 = unpack2(acc[p][2]), v3 = unpack2(acc[p][3]);
        int r0 = bm + (ty << 4) + (p << 1);
        if (!TR) {
            *(float4*)(C + (size_t)r0 * N + bn + (tx << 2)) = make_float4(v0.x + b0, v1.x + b1, v2.x + b2, v3.x + b3);
            *(float4*)(C + (size_t)(r0 + 1) * N + bn + (tx << 2)) = make_float4(v0.y + b0, v1.y + b1, v2.y + b2, v3.y + b3);
        } else {
            int t = r0 >> 5, b = r0 & 31;
            size_t base = (size_t)t * G4 * 32 + b;
            int n0 = bn + (tx << 2);
            *(float2*)(C + base + (size_t)(n0 + 0) * 32) = make_float2(v0.x + b0, v0.y + b0);
            *(float2*)(C + base + (size_t)(n0 + 1) * 32) = make_float2(v1.x + b1, v1.y + b1);
            *(float2*)(C + base + (size_t)(n0 + 2) * 32) = make_float2(v2.x + b2, v2.y + b2);
            *(float2*)(C + base + (size_t)(n0 + 3) * 32) = make_float2(v3.x + b3, v3.y + b3);
        }
    }
}

// ---------------- init ----------------
__global__ void k_init() {
    int i = blockIdx.x * 256 + threadIdx.x;
    if (i < 2 * 1024 * BB) d_hcat[i] = 0.f;
    if (i < NCTA) d_flags2[i] = 0;
}

// ---------------- fused 2-layer persistent LSTM ----------------
// 24 half-slices (64 k each): hs 0-7 = L0, hs 8-23 = L1 concat [wih1|whh1].
// Warp w handles hs {w, 8+w, 16+w}; hs w and 8+w share h loads (same k-range).
// Gate phase: warps 0-3 -> L0 cell (time e), warps 4-7 -> L1 cell (time e-1).
__global__ void __launch_bounds__(256, 1) k_fused(
    const float* __restrict__ xgT, const float* __restrict__ whh0,
    const float* __restrict__ wih1, const float* __restrict__ whh1,
    const float* __restrict__ bl1, float* __restrict__ h1sT)
{
    extern __shared__ ULL smw[];                 // 12288 ULL weights
    float* gbufA = (float*)(smw + 12288);        // 8 hs * 16 * 32
    float* gbufB = gbufA + 4096;                 // 16 hs * 16 * 32
    const int tid = threadIdx.x, cta = blockIdx.x, jbase = cta * 4;
    const int lane = tid & 31, wid = tid >> 5;

    for (int i = tid; i < 12288; i += 256) {
        int hs = i >> 9, p = (i >> 6) & 7, kl = i & 63;
        int row0 = (p >> 1) * HH + jbase + (p & 1) * 2;
        const float* s0;
        if (hs < 8) s0 = whh0 + (size_t)row0 * HH + hs * 64 + kl;
        else {
            int kg = (hs - 8) * 64 + kl;
            s0 = (kg < HH) ? wih1 + (size_t)row0 * HH + kg
                           : whh1 + (size_t)row0 * HH + kg - HH;
        }
        smw[i] = pack2(s0[0], s0[HH]);
    }
    __syncthreads();

    float c0 = 0.f, c1 = 0.f, bv0 = 0.f, bv1 = 0.f, bv2 = 0.f, bv3 = 0.f;
    if (wid >= 4) {
        int j = jbase + (wid - 4);
        bv0 = bl1[j]; bv1 = bl1[HH + j]; bv2 = bl1[2 * HH + j]; bv3 = bl1[3 * HH + j];
    }

    for (int e = 0; e <= TP; e++) {
        const int slot = e & 1;
        float xv0 = 0.f, xv1 = 0.f, xv2 = 0.f, xv3 = 0.f;
        if (wid < 4 && e < TP) {
            const float* xp = xgT + ((size_t)e * G4 + jbase + wid) * 32 + lane;
            xv0 = __ldg(xp);            xv1 = __ldg(xp + HH * 32);
            xv2 = __ldg(xp + 1024 * 32); xv3 = __ldg(xp + 1536 * 32);
        }
        if (e > 0) {
            if (tid < NCTA) while (ld_acq(&d_flags2[tid]) < e) __nanosleep(32);
        }
        __syncthreads();

        const float* hbase = d_hcat + slot * 32768 + lane;
        // ---- phase 1: k in [wid*64, wid*64+64): L0 hs=wid + L1 hs=8+wid (shared h)
        {
            ULL a[16];
#pragma unroll
            for (int i = 0; i < 16; i++) a[i] = 0ULL;
            const float* hp = hbase + (wid * 64) * 32;
            const ULL* wA = smw + (size_t)wid * 512;
            const ULL* wB = smw + (size_t)(8 + wid) * 512;
            float hn[8], hc[8];
#pragma unroll
            for (int q = 0; q < 8; q++) hn[q] = __ldcg(hp + q * 32);
#pragma unroll
            for (int blk = 0; blk < 8; blk++) {
#pragma unroll
                for (int q = 0; q < 8; q++) hc[q] = hn[q];
                if (blk < 7) {
#pragma unroll
                    for (int q = 0; q < 8; q++) hn[q] = __ldcg(hp + ((blk + 1) * 8 + q) * 32);
                }
                int kb = blk * 8;
#pragma unroll
                for (int q = 0; q < 8; q += 2) {
                    ULL h0 = pack2(hc[q], hc[q]), h1 = pack2(hc[q + 1], hc[q + 1]);
#pragma unroll
                    for (int p = 0; p < 8; p++) {
                        ulonglong2 w2 = *(const ulonglong2*)(wA + p * 64 + kb + q);
                        a[p] = ffma2(w2.x, h0, a[p]); a[p] = ffma2(w2.y, h1, a[p]);
                    }
#pragma unroll
                    for (int p = 0; p < 8; p++) {
                        ulonglong2 w2 = *(const ulonglong2*)(wB + p * 64 + kb + q);
                        a[8 + p] = ffma2(w2.x, h0, a[8 + p]); a[8 + p] = ffma2(w2.y, h1, a[8 + p]);
                    }
                }
            }
#pragma unroll
            for (int p = 0; p < 8; p++) {
                int r = (p >> 1) * 4 + (p & 1) * 2;
                float2 v = unpack2(a[p]);
                gbufA[wid * 512 + r * 32 + lane] = v.x;
                gbufA[wid * 512 + (r + 1) * 32 + lane] = v.y;
                float2 u2 = unpack2(a[8 + p]);
                gbufB[wid * 512 + r * 32 + lane] = u2.x;
                gbufB[wid * 512 + (r + 1) * 32 + lane] = u2.y;
            }
        }
        // ---- phase 2: k in [512+wid*64, +64): L1 hs=16+wid
        {
            ULL a[8];
#pragma unroll
            for (int i = 0; i < 8; i++) a[i] = 0ULL;
            const float* hp = hbase + (512 + wid * 64) * 32;
            const ULL* wC = smw + (size_t)(16 + wid) * 512;
            float hn[8], hc[8];
#pragma unroll
            for (int q = 0; q < 8; q++) hn[q] = __ldcg(hp + q * 32);
#pragma unroll
            for (int blk = 0; blk < 8; blk++) {
#pragma unroll
                for (int q = 0; q < 8; q++) hc[q] = hn[q];
                if (blk < 7) {
#pragma unroll
                    for (int q = 0; q < 8; q++) hn[q] = __ldcg(hp + ((blk + 1) * 8 + q) * 32);
                }
                int kb = blk * 8;
#pragma unroll
                for (int q = 0; q < 8; q += 2) {
                    ULL h0 = pack2(hc[q], hc[q]), h1 = pack2(hc[q + 1], hc[q + 1]);
#pragma unroll
                    for (int p = 0; p < 8; p++) {
                        ulonglong2 w2 = *(const ulonglong2*)(wC + p * 64 + kb + q);
                        a[p] = ffma2(w2.x, h0, a[p]); a[p] = ffma2(w2.y, h1, a[p]);
                    }
                }
            }
#pragma unroll
            for (int p = 0; p < 8; p++) {
                int r = (p >> 1) * 4 + (p & 1) * 2;
                float2 v = unpack2(a[p]);
                gbufB[(8 + wid) * 512 + r * 32 + lane] = v.x;
                gbufB[(8 + wid) * 512 + (r + 1) * 32 + lane] = v.y;
            }
        }
        __syncthreads();

        if (wid < 4) {
            if (e < TP) {       // layer-0 cell, time e
                float g0 = xv0, g1 = xv1, g2 = xv2, g3 = xv3;
#pragma unroll
                for (int s = 0; s < 8; s++) {
                    const float* q = gbufA + s * 512 + wid * 32 + lane;
                    g0 += q[0]; g1 += q[128]; g2 += q[256]; g3 += q[384];
                }
                float iv = fsigmoid(g0), fv = fsigmoid(g1), gg = ftanh(g2), ov = fsigmoid(g3);
                c0 = fmaf(fv, c0, iv * gg);
                d_hcat[(slot ^ 1) * 32768 + (jbase + wid) * 32 + lane] = ov * ftanh(c0);
            }
        } else {
            if (e >= 1) {       // layer-1 cell, time e-1
                int u = wid - 4;
                float g0 = bv0, g1 = bv1, g2 = bv2, g3 = bv3;
#pragma unroll
                for (int s = 0; s < 16; s++) {
                    const float* q = gbufB + s * 512 + u * 32 + lane;
                    g0 += q[0]; g1 += q[128]; g2 += q[256]; g3 += q[384];
                }
                float iv = fsigmoid(g0), fv = fsigmoid(g1), gg = ftanh(g2), ov = fsigmoid(g3);
                c1 = fmaf(fv, c1, iv * gg);
                float hv = ov * ftanh(c1);
                d_hcat[(slot ^ 1) * 32768 + (512 + jbase + u) * 32 + lane] = hv;
                h1sT[((size_t)(e - 1) * HH + jbase + u) * 32 + lane] = hv;
            }
        }
        if (e < TP) {
            __syncthreads();
            if (tid == 0) st_rel(&d_flags2[cta], e + 1);
        }
    }
}

// ---------------- head: block per t, reads h1sT[t][j][b] ----------------
__global__ void k_head(const float* __restrict__ wout, const float* __restrict__ bout,
                       const float* __restrict__ hsT, float* __restrict__ out)
{
    extern __shared__ float smh[];      // 16384 h + 3072 w
    float* hsm = smh;
    float* ws  = smh + 16384;
    int tid = threadIdx.x, t = blockIdx.x;
    const float4* src = (const float4*)(hsT + (size_t)t * 16384);
    for (int i = tid; i < 4096; i += 256) ((float4*)hsm)[i] = src[i];
    for (int i = tid; i < 3072; i += 256) ws[i] = wout[i];
    __syncthreads();
    int o = tid >> 5, b = tid & 31;
    if (o < OUTD) {
        float s = 0.f;
        const float* wp = ws + o * HH;
        const float* hp = hsm + b;
#pragma unroll 8
        for (int j = 0; j < HH; j++) s = fmaf(wp[j], hp[j * 32], s);
        out[((size_t)b * TP + t) * OUTD + o] = s + bout[o];
    }
}

// ---------------- launch ----------------
extern "C" void kernel_launch(void* const* d_in, const int* in_sizes, int n_in,
                              void* d_out, int out_size) {
    (void)in_sizes; (void)n_in; (void)out_size;
    const float* x    = (const float*)d_in[0];
    const float* cw1  = (const float*)d_in[1];
    const float* cb1  = (const float*)d_in[2];
    const float* cw2  = (const float*)d_in[3];
    const float* cb2  = (const float*)d_in[4];
    const float* cw3  = (const float*)d_in[5];
    const float* cb3  = (const float*)d_in[6];
    const float* cbk  = (const float*)d_in[7];
    const float* wih0 = (const float*)d_in[8];
    const float* whh0 = (const float*)d_in[9];
    const float* bl0  = (const float*)d_in[10];
    const float* wih1 = (const float*)d_in[11];
    const float* whh1 = (const float*)d_in[12];
    const float* bl1  = (const float*)d_in[13];
    const float* wout = (const float*)d_in[14];
    const float* bout = (const float*)d_in[15];
    float* out = (float*)d_out;

    const int smem_c2 = (16384 + 64 * 67 + 64) * 4;
    const int smem_c3 = (12288 + 64 * 34 + 64) * 4;
    const int smem_q  = (16384 + 256) * 4;
    const int smem_f  = 12288 * 8 + (4096 + 8192) * 4;   // 147456
    const int smem_h  = (16384 + 3072) * 4;              // 77824

    static float *pc1 = nullptr, *pc2, *pze, *pz, *pxgT, *ph1sT;
    if (!pc1) {
        cudaGetSymbolAddress((void**)&pc1,   d_c1);
        cudaGetSymbolAddress((void**)&pc2,   d_c2);
        cudaGetSymbolAddress((void**)&pze,   d_ze);
        cudaGetSymbolAddress((void**)&pz,    d_z);
        cudaGetSymbolAddress((void**)&pxgT,  d_xgT);
        cudaGetSymbolAddress((void**)&ph1sT, d_h1sT);
        cudaFuncSetAttribute((const void*)k_conv<4,2,2048,false>, cudaFuncAttributeMaxDynamicSharedMemorySize, smem_c2);
        cudaFuncSetAttribute((const void*)k_conv<3,1,1024,true>,  cudaFuncAttributeMaxDynamicSharedMemorySize, smem_c3);
        cudaFuncSetAttribute((const void*)k_quant, cudaFuncAttributeMaxDynamicSharedMemorySize, smem_q);
        cudaFuncSetAttribute((const void*)k_fused, cudaFuncAttributeMaxDynamicSharedMemorySize, smem_f);
        cudaFuncSetAttribute((const void*)k_head,  cudaFuncAttributeMaxDynamicSharedMemorySize, smem_h);
    }

    k_mean <<<(BB * TT) / 256, 256>>>(x);
    k_conv1<<<dim3(8, BB), 256>>>(cw1, cb1);
    k_conv<4,2,2048,false><<<dim3(32, BB), 256, smem_c2>>>(pc1, cw2, cb2, pc2);
    k_conv<3,1,1024,true> <<<dim3(32, BB), 256, smem_c3>>>(pc2, cw3, cb3, pze);
    k_quant<<<(BB * TP) / 128, 128, smem_q>>>(cbk);

    // xgT = z @ wih0^T + bl0, stored [t][n][b]
    k_gemm2<true><<<dim3(G4 / 128, (BB * TP) / 128), 256>>>(pz, wih0, bl0, pxgT, BB * TP, G4, DD);
    k_init<<<256, 256>>>();
    k_fused<<<NCTA, 256, smem_f>>>(pxgT, whh0, wih1, whh1, bl1, ph1sT);

    k_head<<<TP, 256, smem_h>>>(wout, bout, ph1sT, out);
}

// round 15
// speedup vs baseline: 1.5416x; 1.5416x over previous
#include <cuda_runtime.h>
#include <math.h>
#include <stdint.h>
#include <stddef.h>

#define BB   32
#define TT   4096
#define TP   1024
#define DD   64
#define HH   512
#define G4   2048
#define OUTD 6
#define NCTA 128

typedef unsigned long long ULL;
__device__ __forceinline__ ULL ffma2(ULL a, ULL b, ULL c) {
    ULL d; asm("fma.rn.f32x2 %0, %1, %2, %3;" : "=l"(d) : "l"(a), "l"(b), "l"(c)); return d;
}
__device__ __forceinline__ ULL pack2(float lo, float hi) {
    ULL r; asm("mov.b64 %0, {%1, %2};" : "=l"(r) : "f"(lo), "f"(hi)); return r;
}
__device__ __forceinline__ float2 unpack2(ULL v) {
    float2 r; asm("mov.b64 {%0, %1}, %2;" : "=f"(r.x), "=f"(r.y) : "l"(v)); return r;
}
__device__ __forceinline__ float fsigmoid(float x) { return __fdividef(1.f, 1.f + __expf(-x)); }
__device__ __forceinline__ float ftanh(float x) { return 1.f - __fdividef(2.f, __expf(2.f * x) + 1.f); }
__device__ __forceinline__ int ldflag(const int* p) {
    int v; asm volatile("ld.global.cg.b32 %0, [%1];" : "=r"(v) : "l"(p) : "memory"); return v;
}
__device__ __forceinline__ void stflag(int* p, int v) {
    asm volatile("st.global.cg.b32 [%0], %1;" :: "l"(p), "r"(v) : "memory");
}

// ---------------- scratch ----------------
static __device__ float d_c1 [BB * 64 * 2048];
static __device__ float d_c2 [BB * 64 * 1024];
static __device__ float d_z  [BB * TP * DD];                 // [(b*TP+t)][64]
static __device__ float d_xg [(size_t)BB * TP * G4];         // [(b*TP+t)][n]
static __device__ float d_h1sT[(size_t)TP * HH * BB];        // [t][j][b]
static __device__ float d_hcat[2 * 1024 * BB];               // [slot][kk][b]
static __device__ int   d_flags2[NCTA];

// ---------------- init (launch #1) ----------------
__global__ void k_init() {
    int i = blockIdx.x * 256 + threadIdx.x;
    if (i < 2 * 1024 * BB) d_hcat[i] = 0.f;
    if (i < NCTA) d_flags2[i] = 0;
}

// ---------------- mean + conv1 fused (launch #2) ----------------
__global__ void k_mc1(const float* __restrict__ x, const float* __restrict__ w1,
                      const float* __restrict__ b1) {
    __shared__ float sig_s[520], ws[256], bs[64];
    int tid = threadIdx.x, b = blockIdx.y, p0 = blockIdx.x * 256;
    if (tid < 256) ws[tid] = w1[tid];
    if (tid < 64)  bs[tid] = b1[tid];
    for (int i = tid; i < 515; i += 256) {
        int q = 2 * p0 - 1 + i;
        float s = 0.f;
        if (q >= 0 && q < TT) {
            const float4* xp = (const float4*)(x + ((size_t)b * TT + q) * 64);
#pragma unroll
            for (int r = 0; r < 16; r++) { float4 v = xp[r]; s += v.x + v.y + v.z + v.w; }
        }
        sig_s[i] = s * (1.0f / 64.0f);
    }
    __syncthreads();
    float in[4];
#pragma unroll
    for (int j = 0; j < 4; j++) in[j] = sig_s[2 * tid + j];
    int p = p0 + tid;
    for (int o = 0; o < 64; o++) {
        float a = bs[o];
#pragma unroll
        for (int j = 0; j < 4; j++) a = fmaf(ws[o * 4 + j], in[j], a);
        d_c1[((size_t)(b * 64 + o)) * 2048 + p] = fmaxf(a, 0.f);
    }
}

// ---------------- conv2 (launch #3) ----------------
__global__ void k_conv2(const float* __restrict__ w2, const float* __restrict__ b2) {
    extern __shared__ float sm2[];
    float* ws    = sm2;                 // 16384
    float* patch = ws + 16384;          // 64*67
    float* bs    = patch + 64 * 67;
    int tid = threadIdx.x;
    for (int i = tid; i < 16384; i += 256) ws[i] = w2[i];
    if (tid < 64) bs[tid] = b2[tid];
    int bb = blockIdx.y, p0 = blockIdx.x * 32, q0 = 2 * p0 - 1;
    for (int i = tid; i < 64 * 67; i += 256) {
        int c = i / 67, q = q0 + i % 67;
        patch[i] = (q >= 0 && q < 2048) ? d_c1[((size_t)(bb * 64 + c)) * 2048 + q] : 0.f;
    }
    __syncthreads();
    int po = tid & 31, og = tid >> 5;
    float acc[8];
#pragma unroll
    for (int i = 0; i < 8; i++) acc[i] = 0.f;
    for (int c = 0; c < 64; c++) {
        const float* pc = patch + c * 67 + 2 * po;
        float i0 = pc[0], i1 = pc[1], i2 = pc[2], i3 = pc[3];
#pragma unroll
        for (int oi = 0; oi < 8; oi++) {
            const float* wp = &ws[((og * 8 + oi) * 64 + c) * 4];
            acc[oi] = fmaf(wp[0], i0, fmaf(wp[1], i1, fmaf(wp[2], i2, fmaf(wp[3], i3, acc[oi]))));
        }
    }
#pragma unroll
    for (int oi = 0; oi < 8; oi++) {
        int o = og * 8 + oi;
        d_c2[((size_t)(bb * 64 + o)) * 1024 + p0 + po] = fmaxf(acc[oi] + bs[o], 0.f);
    }
}

// ---------------- conv3 + quantize fused (launch #4) ----------------
// block: 32 positions of one batch. Computes ze, argmin over codebook, writes d_z.
__global__ void k_c3q(const float* __restrict__ w3, const float* __restrict__ b3,
                      const float* __restrict__ cb) {
    extern __shared__ float sm3[];
    float* ws    = sm3;                    // 12288
    float* patch = ws + 12288;             // 64*34 = 2176
    float* bs    = patch + 2176;           // 64
    float* zs    = bs + 64;                // 32*65 = 2080
    float* cbs   = zs + 2080;              // 256*65 = 16640
    float* cn    = cbs + 16640;            // 256
    int tid = threadIdx.x;
    for (int i = tid; i < 12288; i += 256) ws[i] = w3[i];
    if (tid < 64) bs[tid] = b3[tid];
    for (int i = tid; i < 16384; i += 256) cbs[(i >> 6) * 65 + (i & 63)] = cb[i];
    int bb = blockIdx.y, p0 = blockIdx.x * 32, q0 = p0 - 1;
    for (int i = tid; i < 64 * 34; i += 256) {
        int c = i / 34, q = q0 + i % 34;
        patch[i] = (q >= 0 && q < 1024) ? d_c2[((size_t)(bb * 64 + c)) * 1024 + q] : 0.f;
    }
    __syncthreads();
    // code norms
    {
        float s = 0.f;
        const float* cp = cbs + tid * 65;
#pragma unroll 8
        for (int d = 0; d < 64; d++) s = fmaf(cp[d], cp[d], s);
        cn[tid] = s;
    }
    // conv3
    int po = tid & 31, og = tid >> 5;
    float acc[8];
#pragma unroll
    for (int i = 0; i < 8; i++) acc[i] = 0.f;
    for (int c = 0; c < 64; c++) {
        const float* pc = patch + c * 34 + po;
        float i0 = pc[0], i1 = pc[1], i2 = pc[2];
#pragma unroll
        for (int oi = 0; oi < 8; oi++) {
            const float* wp = &ws[((og * 8 + oi) * 64 + c) * 3];
            acc[oi] = fmaf(wp[0], i0, fmaf(wp[1], i1, fmaf(wp[2], i2, acc[oi])));
        }
    }
#pragma unroll
    for (int oi = 0; oi < 8; oi++) zs[po * 65 + og * 8 + oi] = acc[oi] + bs[og * 8 + oi];
    __syncthreads();
    // quantize: 8 threads per position, codes interleaved c = sub + cc*8
    int pos = tid >> 3, sub = tid & 7;
    const float* zp = zs + pos * 65;
    float szz = 0.f;
#pragma unroll 8
    for (int d = 0; d < 64; d++) szz = fmaf(zp[d], zp[d], szz);
    ULL best = ~0ULL;
    for (int cc = 0; cc < 32; cc++) {
        int c = sub + cc * 8;
        const float* cp = cbs + c * 65;
        float dot = 0.f;
#pragma unroll 8
        for (int d = 0; d < 64; d++) dot = fmaf(cp[d], zp[d], dot);
        float dist = szz - 2.f * dot + cn[c];
        ULL key = ((ULL)__float_as_uint(fmaxf(dist, 0.f)) << 32) | (unsigned)c;
        if (key < best) best = key;
    }
#pragma unroll
    for (int off = 4; off; off >>= 1) {
        ULL o = __shfl_xor_sync(0xFFFFFFFFu, best, off);
        if (o < best) best = o;
    }
    int c = (int)(best & 0xFFFFFFFFu);
    float* zo = d_z + ((size_t)bb * TP + p0 + pos) * 64;
    const float* cp = cbs + c * 65;
#pragma unroll
    for (int r = 0; r < 8; r++) zo[sub * 8 + r] = cp[sub * 8 + r];
}

// ---------------- GEMM (f32x2): C = A[M,K]*B[N,K]^T + bias (launch #5) ----------------
__global__ void __launch_bounds__(256, 2) k_gemm2(
    const float* __restrict__ A, const float* __restrict__ B,
    const float* __restrict__ bias, float* __restrict__ C, int M, int N, int K)
{
    __shared__ float As[16][132];
    __shared__ float Bs[16][128];
    int tid = threadIdx.x;
    int bm = blockIdx.y << 7, bn = blockIdx.x << 7;
    int ty = tid >> 5, tx = tid & 31;
    ULL acc[8][4];
#pragma unroll
    for (int p = 0; p < 8; p++)
#pragma unroll
        for (int j = 0; j < 4; j++) acc[p][j] = 0ULL;
    for (int k0 = 0; k0 < K; k0 += 16) {
        __syncthreads();
#pragma unroll
        for (int q = 0; q < 2; q++) {
            int i = tid * 2 + q, r = i >> 2, c4 = (i & 3) << 2;
            float4 av = *(const float4*)(A + (size_t)(bm + r) * K + k0 + c4);
            As[c4 + 0][r] = av.x; As[c4 + 1][r] = av.y; As[c4 + 2][r] = av.z; As[c4 + 3][r] = av.w;
            float4 bv = *(const float4*)(B + (size_t)(bn + r) * K + k0 + c4);
            Bs[c4 + 0][r] = bv.x; Bs[c4 + 1][r] = bv.y; Bs[c4 + 2][r] = bv.z; Bs[c4 + 3][r] = bv.w;
        }
        __syncthreads();
#pragma unroll 4
        for (int k = 0; k < 16; k++) {
            const ulonglong2* ap = (const ulonglong2*)&As[k][ty << 4];
            ulonglong2 aA = ap[0], aB2 = ap[1], aC = ap[2], aD = ap[3];
            float4 b4 = *(const float4*)&Bs[k][tx << 2];
            ULL d0 = pack2(b4.x, b4.x), d1 = pack2(b4.y, b4.y);
            ULL d2 = pack2(b4.z, b4.z), d3 = pack2(b4.w, b4.w);
#define ROWF(p, P) \
            acc[p][0] = ffma2(P, d0, acc[p][0]); acc[p][1] = ffma2(P, d1, acc[p][1]); \
            acc[p][2] = ffma2(P, d2, acc[p][2]); acc[p][3] = ffma2(P, d3, acc[p][3]);
            ROWF(0, aA.x)  ROWF(1, aA.y)  ROWF(2, aB2.x) ROWF(3, aB2.y)
            ROWF(4, aC.x)  ROWF(5, aC.y)  ROWF(6, aD.x)  ROWF(7, aD.y)
#undef ROWF
        }
    }
    float b0 = bias[bn + (tx << 2)], b1 = bias[bn + (tx << 2) + 1];
    float b2 = bias[bn + (tx << 2) + 2], b3 = bias[bn + (tx << 2) + 3];
#pragma unroll
    for (int p = 0; p < 8; p++) {
        float2 v0 = unpack2(acc[p][0]), v1 = unpack2(acc[p][1]);
        float2 v2 = unpack2(acc[p][2]), v3 = unpack2(acc[p][3]);
        int r0 = bm + (ty << 4) + (p << 1);
        *(float4*)(C + (size_t)r0 * N + bn + (tx << 2)) = make_float4(v0.x + b0, v1.x + b1, v2.x + b2, v3.x + b3);
        *(float4*)(C + (size_t)(r0 + 1) * N + bn + (tx << 2)) = make_float4(v0.y + b0, v1.y + b1, v2.y + b2, v3.y + b3);
    }
}

// ---------------- fused 2-layer persistent LSTM (launch #6) ----------------
// smem weights (f32x2 row-pairs, [p*512+k]): [0,4096) whh0, [4096,8192) wih1, [8192,12288) whh1.
// Heavy warp w<4: L0 k in [w*128,+128) + L1(wih1) k in [w*128,+64)   = 1536 ffma2
// Light warp v=w-4: L1(wih1) k in [v*128+64,+64) + L1(whh1) k in [v*128,+128) = 1536 ffma2
__global__ void __launch_bounds__(256, 1) k_fused(
    const float* __restrict__ xg, const float* __restrict__ whh0,
    const float* __restrict__ wih1, const float* __restrict__ whh1,
    const float* __restrict__ bl1, float* __restrict__ h1sT)
{
    extern __shared__ ULL smw[];                 // 12288 ULL
    float* gbufA = (float*)(smw + 12288);        // 4 * 16 * 32
    float* gbufB = gbufA + 2048;                 // 8 * 16 * 32
    const int tid = threadIdx.x, cta = blockIdx.x, jbase = cta * 4;
    const int lane = tid & 31, wid = tid >> 5;

    for (int i = tid; i < 12288; i += 256) {
        int sel = i >> 12, p = (i >> 9) & 7, k = i & 511;
        int row0 = (p >> 1) * HH + jbase + (p & 1) * 2;
        const float* s0 = (sel == 0 ? whh0 : sel == 1 ? wih1 : whh1) + (size_t)row0 * HH + k;
        smw[i] = pack2(s0[0], s0[HH]);
    }
    __syncthreads();

    float c0 = 0.f, c1 = 0.f, bv0 = 0.f, bv1 = 0.f, bv2 = 0.f, bv3 = 0.f;
    if (wid >= 4) {
        int j = jbase + (wid - 4);
        bv0 = bl1[j]; bv1 = bl1[HH + j]; bv2 = bl1[2 * HH + j]; bv3 = bl1[3 * HH + j];
    }

    for (int e = 0; e <= TP; e++) {
        const int slot = e & 1;
        float xv0 = 0.f, xv1 = 0.f, xv2 = 0.f, xv3 = 0.f;
        if (wid < 4 && e < TP) {
            const float* xp = xg + ((size_t)lane * TP + e) * G4 + jbase + wid;
            xv0 = __ldg(xp);           xv1 = __ldg(xp + HH);
            xv2 = __ldg(xp + 2 * HH);  xv3 = __ldg(xp + 3 * HH);
        }
        if (e > 0 && tid < NCTA) {
            while (ldflag(&d_flags2[tid]) < e) __nanosleep(32);
        }
        __syncthreads();

        const float* hb = d_hcat + slot * 32768 + lane;
        if (wid < 4) {
            // ---- heavy: L0 (16 blocks) + wih1 (first 8 blocks)
            ULL A[8], Bc[8];
#pragma unroll
            for (int i = 0; i < 8; i++) { A[i] = 0ULL; Bc[i] = 0ULL; }
            const float* hp = hb + (wid * 128) * 32;
            const int kb0 = wid * 128;
            float hn[8];
#pragma unroll
            for (int q = 0; q < 8; q++) hn[q] = __ldcg(hp + q * 32);
#pragma unroll 1
            for (int blk = 0; blk < 8; blk++) {
                float hc[8];
#pragma unroll
                for (int q = 0; q < 8; q++) hc[q] = hn[q];
#pragma unroll
                for (int q = 0; q < 8; q++) hn[q] = __ldcg(hp + ((blk + 1) * 8 + q) * 32);
                int kk = kb0 + blk * 8;
#pragma unroll
                for (int q = 0; q < 8; q += 2) {
                    ULL h0 = pack2(hc[q], hc[q]), h1 = pack2(hc[q + 1], hc[q + 1]);
#pragma unroll
                    for (int p = 0; p < 8; p++) {
                        ulonglong2 w2 = *(const ulonglong2*)(smw + p * 512 + kk + q);
                        A[p] = ffma2(w2.x, h0, A[p]); A[p] = ffma2(w2.y, h1, A[p]);
                    }
#pragma unroll
                    for (int p = 0; p < 8; p++) {
                        ulonglong2 w2 = *(const ulonglong2*)(smw + 4096 + p * 512 + kk + q);
                        Bc[p] = ffma2(w2.x, h0, Bc[p]); Bc[p] = ffma2(w2.y, h1, Bc[p]);
                    }
                }
            }
#pragma unroll 1
            for (int blk = 8; blk < 16; blk++) {
                float hc[8];
#pragma unroll
                for (int q = 0; q < 8; q++) hc[q] = hn[q];
                if (blk < 15) {
#pragma unroll
                    for (int q = 0; q < 8; q++) hn[q] = __ldcg(hp + ((blk + 1) * 8 + q) * 32);
                }
                int kk = kb0 + blk * 8;
#pragma unroll
                for (int q = 0; q < 8; q += 2) {
                    ULL h0 = pack2(hc[q], hc[q]), h1 = pack2(hc[q + 1], hc[q + 1]);
#pragma unroll
                    for (int p = 0; p < 8; p++) {
                        ulonglong2 w2 = *(const ulonglong2*)(smw + p * 512 + kk + q);
                        A[p] = ffma2(w2.x, h0, A[p]); A[p] = ffma2(w2.y, h1, A[p]);
                    }
                }
            }
#pragma unroll
            for (int p = 0; p < 8; p++) {
                int r = (p >> 1) * 4 + (p & 1) * 2;
                float2 va = unpack2(A[p]);
                gbufA[wid * 512 + r * 32 + lane] = va.x;
                gbufA[wid * 512 + (r + 1) * 32 + lane] = va.y;
                float2 vb = unpack2(Bc[p]);
                gbufB[wid * 512 + r * 32 + lane] = vb.x;
                gbufB[wid * 512 + (r + 1) * 32 + lane] = vb.y;
            }
        } else {
            // ---- light: wih1 k in [v*128+64,+64) (h0) + whh1 k in [v*128,+128) (h1)
            const int v = wid - 4;
            ULL Bc[8];
#pragma unroll
            for (int i = 0; i < 8; i++) Bc[i] = 0ULL;
            const float* hp1 = hb + (v * 128 + 64) * 32;
            const float* hp2 = hb + (512 + v * 128) * 32;
            float hn[8], hn2[8];
#pragma unroll
            for (int q = 0; q < 8; q++) hn[q] = __ldcg(hp1 + q * 32);
#pragma unroll
            for (int q = 0; q < 8; q++) hn2[q] = __ldcg(hp2 + q * 32);
            const int kb1 = v * 128 + 64;
#pragma unroll 1
            for (int blk = 0; blk < 8; blk++) {
                float hc[8];
#pragma unroll
                for (int q = 0; q < 8; q++) hc[q] = hn[q];
                if (blk < 7) {
#pragma unroll
                    for (int q = 0; q < 8; q++) hn[q] = __ldcg(hp1 + ((blk + 1) * 8 + q) * 32);
                }
                int kk = kb1 + blk * 8;
#pragma unroll
                for (int q = 0; q < 8; q += 2) {
                    ULL h0 = pack2(hc[q], hc[q]), h1 = pack2(hc[q + 1], hc[q + 1]);
#pragma unroll
                    for (int p = 0; p < 8; p++) {
                        ulonglong2 w2 = *(const ulonglong2*)(smw + 4096 + p * 512 + kk + q);
                        Bc[p] = ffma2(w2.x, h0, Bc[p]); Bc[p] = ffma2(w2.y, h1, Bc[p]);
                    }
                }
            }
            const int kb2 = v * 128;
#pragma unroll 1
            for (int blk = 0; blk < 16; blk++) {
                float hc[8];
#pragma unroll
                for (int q = 0; q < 8; q++) hc[q] = hn2[q];
                if (blk < 15) {
#pragma unroll
                    for (int q = 0; q < 8; q++) hn2[q] = __ldcg(hp2 + ((blk + 1) * 8 + q) * 32);
                }
                int kk = kb2 + blk * 8;
#pragma unroll
                for (int q = 0; q < 8; q += 2) {
                    ULL h0 = pack2(hc[q], hc[q]), h1 = pack2(hc[q + 1], hc[q + 1]);
#pragma unroll
                    for (int p = 0; p < 8; p++) {
                        ulonglong2 w2 = *(const ulonglong2*)(smw + 8192 + p * 512 + kk + q);
                        Bc[p] = ffma2(w2.x, h0, Bc[p]); Bc[p] = ffma2(w2.y, h1, Bc[p]);
                    }
                }
            }
#pragma unroll
            for (int p = 0; p < 8; p++) {
                int r = (p >> 1) * 4 + (p & 1) * 2;
                float2 vb = unpack2(Bc[p]);
                gbufB[(4 + v) * 512 + r * 32 + lane] = vb.x;
                gbufB[(4 + v) * 512 + (r + 1) * 32 + lane] = vb.y;
            }
        }
        __syncthreads();

        if (wid < 4) {
            if (e < TP) {          // layer-0 cell, time e
                float g0 = xv0, g1 = xv1, g2 = xv2, g3 = xv3;
#pragma unroll
                for (int s = 0; s < 4; s++) {
                    const float* q = gbufA + s * 512 + wid * 32 + lane;
                    g0 += q[0]; g1 += q[128]; g2 += q[256]; g3 += q[384];
                }
                float iv = fsigmoid(g0), fv = fsigmoid(g1), gg = ftanh(g2), ov = fsigmoid(g3);
                c0 = fmaf(fv, c0, iv * gg);
                d_hcat[(slot ^ 1) * 32768 + (jbase + wid) * 32 + lane] = ov * ftanh(c0);
            }
        } else {
            if (e >= 1) {          // layer-1 cell, time e-1
                int u = wid - 4;
                float g0 = bv0, g1 = bv1, g2 = bv2, g3 = bv3;
#pragma unroll
                for (int s = 0; s < 8; s++) {
                    const float* q = gbufB + s * 512 + u * 32 + lane;
                    g0 += q[0]; g1 += q[128]; g2 += q[256]; g3 += q[384];
                }
                float iv = fsigmoid(g0), fv = fsigmoid(g1), gg = ftanh(g2), ov = fsigmoid(g3);
                c1 = fmaf(fv, c1, iv * gg);
                float hv = ov * ftanh(c1);
                d_hcat[(slot ^ 1) * 32768 + (512 + jbase + u) * 32 + lane] = hv;
                h1sT[((size_t)(e - 1) * HH + jbase + u) * 32 + lane] = hv;
            }
        }
        if (e < TP) {
            __threadfence();
            __syncthreads();
            if (tid == 0) stflag(&d_flags2[cta], e + 1);
        }
    }
}

// ---------------- head: block per t (launch #7) ----------------
__global__ void k_head(const float* __restrict__ wout, const float* __restrict__ bout,
                       const float* __restrict__ hsT, float* __restrict__ out)
{
    extern __shared__ float smh[];      // 16384 h + 3072 w
    float* hsm = smh;
    float* ws  = smh + 16384;
    int tid = threadIdx.x, t = blockIdx.x;
    const float4* src = (const float4*)(hsT + (size_t)t * 16384);
    for (int i = tid; i < 4096; i += 256) ((float4*)hsm)[i] = src[i];
    for (int i = tid; i < 3072; i += 256) ws[i] = wout[i];
    __syncthreads();
    int o = tid >> 5, b = tid & 31;
    if (o < OUTD) {
        float s = 0.f;
        const float* wp = ws + o * HH;
        const float* hp = hsm + b;
#pragma unroll 8
        for (int j = 0; j < HH; j++) s = fmaf(wp[j], hp[j * 32], s);
        out[((size_t)b * TP + t) * OUTD + o] = s + bout[o];
    }
}

// ---------------- launch ----------------
extern "C" void kernel_launch(void* const* d_in, const int* in_sizes, int n_in,
                              void* d_out, int out_size) {
    (void)in_sizes; (void)n_in; (void)out_size;
    const float* x    = (const float*)d_in[0];
    const float* cw1  = (const float*)d_in[1];
    const float* cb1  = (const float*)d_in[2];
    const float* cw2  = (const float*)d_in[3];
    const float* cb2  = (const float*)d_in[4];
    const float* cw3  = (const float*)d_in[5];
    const float* cb3  = (const float*)d_in[6];
    const float* cbk  = (const float*)d_in[7];
    const float* wih0 = (const float*)d_in[8];
    const float* whh0 = (const float*)d_in[9];
    const float* bl0  = (const float*)d_in[10];
    const float* wih1 = (const float*)d_in[11];
    const float* whh1 = (const float*)d_in[12];
    const float* bl1  = (const float*)d_in[13];
    const float* wout = (const float*)d_in[14];
    const float* bout = (const float*)d_in[15];
    float* out = (float*)d_out;

    const int smem_c2 = (16384 + 64 * 67 + 64) * 4;
    const int smem_q  = (12288 + 2176 + 64 + 2080 + 16640 + 256) * 4;   // 134016
    const int smem_f  = 12288 * 8 + (2048 + 4096) * 4;                  // 122880
    const int smem_h  = (16384 + 3072) * 4;                             // 77824

    static float *pz = nullptr, *pxg, *ph1sT;
    if (!pz) {
        cudaGetSymbolAddress((void**)&pz,    d_z);
        cudaGetSymbolAddress((void**)&pxg,   d_xg);
        cudaGetSymbolAddress((void**)&ph1sT, d_h1sT);
        cudaFuncSetAttribute((const void*)k_conv2, cudaFuncAttributeMaxDynamicSharedMemorySize, smem_c2);
        cudaFuncSetAttribute((const void*)k_c3q,   cudaFuncAttributeMaxDynamicSharedMemorySize, smem_q);
        cudaFuncSetAttribute((const void*)k_fused, cudaFuncAttributeMaxDynamicSharedMemorySize, smem_f);
        cudaFuncSetAttribute((const void*)k_head,  cudaFuncAttributeMaxDynamicSharedMemorySize, smem_h);
    }

    k_init <<<256, 256>>>();                                     // #1
    k_mc1  <<<dim3(8, BB), 256>>>(x, cw1, cb1);                  // #2
    k_conv2<<<dim3(32, BB), 256, smem_c2>>>(cw2, cb2);           // #3
    k_c3q  <<<dim3(32, BB), 256, smem_q>>>(cw3, cb3, cbk);       // #4
    k_gemm2<<<dim3(G4 / 128, (BB * TP) / 128), 256>>>(pz, wih0, bl0, pxg, BB * TP, G4, DD);  // #5
    k_fused<<<NCTA, 256, smem_f>>>(pxg, whh0, wih1, whh1, bl1, ph1sT);                       // #6 (profiled)
    k_head <<<TP, 256, smem_h>>>(wout, bout, ph1sT, out);        // #7
}